// round 15
// baseline (speedup 1.0000x reference)
#include <cuda_runtime.h>

// ce_loss_aux: masked one-hot binary CE.
// R12 geometry (1024 blocks x 256 threads, contiguous 2048-pair chunks,
// 8-position log-products, FMA one-hot selects, int64-atomic tail) with
// 256-bit evict-last loads (ld.global.nc.L2::evict_last.v8.b32): the
// ~33.5MB valid working set fits in the 126MB L2, so graph replays should
// hit L2 (~240cyc) instead of DRAM (~577cyc). v8 also halves LSU ops.

#define NTHREADS 256
#define PPT 8                                   // float4-pairs per thread
#define LD8 (PPT / 2)                           // v8.b32 loads per array
#define CHUNK_PAIRS (NTHREADS * PPT)            // 2048 pairs / block
#define FP_SCALE 1048576.0f                     // 2^20

__device__ unsigned long long g_loss;           // fixed-point loss sum
__device__ int                g_len;            // doc_len sum
__device__ unsigned int       g_counter;        // zero-init; reset by last block

struct F8 { float4 a, b; };

__device__ __forceinline__ F8 ldg_el8(const float4* p) {
    F8 v;
    asm("ld.global.nc.L2::evict_last.v8.b32 {%0,%1,%2,%3,%4,%5,%6,%7}, [%8];"
        : "=f"(v.a.x), "=f"(v.a.y), "=f"(v.a.z), "=f"(v.a.w),
          "=f"(v.b.x), "=f"(v.b.y), "=f"(v.b.z), "=f"(v.b.w)
        : "l"(p));
    return v;
}

__global__ __launch_bounds__(NTHREADS)
void ce_fused_kernel(const float* __restrict__ y_true,
                     const float* __restrict__ y_pred,
                     const int*   __restrict__ doc_len,
                     float* __restrict__ out,
                     int B, int L, int chunksPerRow, int nBlocks)
{
    const int tid   = threadIdx.x;
    const int b     = blockIdx.x / chunksPerRow;
    const int chunk = blockIdx.x - b * chunksPerRow;
    const int d     = __ldg(&doc_len[b]);

    const int pairBase = chunk * CHUNK_PAIRS;
    const int lStart   = pairBase * 2;

    float acc = 0.0f;

    if (lStart < d) {
        const float4* t4 = reinterpret_cast<const float4*>(y_true) + (size_t)b * (L >> 1);
        const float4* p4 = reinterpret_cast<const float4*>(y_pred) + (size_t)b * (L >> 1);

        if (lStart + CHUNK_PAIRS * 2 <= d) {
            // ---- fully valid: 4 x v8.b32 per array (32B each, 32B-aligned:
            //      row base is 64KB-aligned, index 2*(...) even) ----
            F8 t[LD8], p[LD8];
            #pragma unroll
            for (int i = 0; i < LD8; i++)
                t[i] = ldg_el8(&t4[pairBase + 2 * (i * NTHREADS + tid)]);
            #pragma unroll
            for (int i = 0; i < LD8; i++)
                p[i] = ldg_el8(&p4[pairBase + 2 * (i * NTHREADS + tid)]);

            #pragma unroll
            for (int j = 0; j < LD8 / 2; j++) {
                float m = 1.0f;
                #pragma unroll
                for (int i = 2 * j; i < 2 * j + 2; i++) {
                    float s0 = t[i].a.x * p[i].a.x + t[i].a.y * p[i].a.y;
                    float s1 = t[i].a.z * p[i].a.z + t[i].a.w * p[i].a.w;
                    float s2 = t[i].b.x * p[i].b.x + t[i].b.y * p[i].b.y;
                    float s3 = t[i].b.z * p[i].b.z + t[i].b.w * p[i].b.w;
                    m *= (s0 * s1) * (s2 * s3);  // 8 factors >= 1e-4 -> m >= 1e-32
                }
                acc -= __logf(m);
            }
        } else {
            // ---- boundary chunk: per-pair predication on d ----
            #pragma unroll
            for (int i = 0; i < PPT; i++) {
                int pr = pairBase + i * NTHREADS + tid;
                int l0 = pr << 1;
                if (l0 < d) {
                    float4 t = __ldg(&t4[pr]);
                    float4 p = __ldg(&p4[pr]);
                    float s0 = t.x * p.x + t.y * p.y;
                    float s1 = (l0 + 1 < d) ? (t.z * p.z + t.w * p.w) : 1.0f;
                    acc -= __logf(s0 * s1);
                }
            }
        }
    }

    // ---- block reduction ----
    __shared__ float red[NTHREADS / 32];
    #pragma unroll
    for (int o = 16; o > 0; o >>= 1)
        acc += __shfl_down_sync(0xFFFFFFFFu, acc, o);
    if ((tid & 31) == 0) red[tid >> 5] = acc;
    __syncthreads();

    // ---- atomic accumulation (exact integer adds -> deterministic) ----
    __shared__ bool amLast;
    if (tid == 0) {
        float v = 0.0f;
        #pragma unroll
        for (int i = 0; i < NTHREADS / 32; i++) v += red[i];
        unsigned long long q = (unsigned long long)__float2ll_rn(v * FP_SCALE);
        atomicAdd(&g_loss, q);
        if (chunk == 0) atomicAdd(&g_len, d);
        __threadfence();
        unsigned int prev = atomicAdd(&g_counter, 1u);
        amLast = (prev == (unsigned int)(nBlocks - 1));
    }
    __syncthreads();

    // ---- last block: finish from two scalars, reset for graph replay ----
    if (amLast && tid == 0) {
        unsigned long long ls = g_loss;
        int                ln = g_len;
        out[0] = (float)((double)ls / (double)FP_SCALE / (double)ln);
        g_loss    = 0ull;
        g_len     = 0;
        g_counter = 0;
    }
}

extern "C" void kernel_launch(void* const* d_in, const int* in_sizes, int n_in,
                              void* d_out, int out_size)
{
    const float* y_true  = (const float*)d_in[0];
    const float* y_pred  = (const float*)d_in[1];
    const int*   doc_len = (const int*)d_in[2];
    float*       out     = (float*)d_out;

    int B = in_sizes[2];
    int L = in_sizes[0] / (2 * B);

    int pairsPerRow  = L >> 1;
    int chunksPerRow = (pairsPerRow + CHUNK_PAIRS - 1) / CHUNK_PAIRS;
    int nBlocks      = B * chunksPerRow;

    ce_fused_kernel<<<nBlocks, NTHREADS>>>(y_true, y_pred, doc_len, out,
                                           B, L, chunksPerRow, nBlocks);
}

// round 16
// speedup vs baseline: 1.2245x; 1.2245x over previous
#include <cuda_runtime.h>

// ce_loss_aux: masked one-hot binary CE.
// R12 geometry (1024 blocks x 256 threads, contiguous 2048-pair chunks,
// batched float4 loads, 8-position log-products, FMA one-hot selects,
// int64-atomic tail). Boundary chunks now use the SAME batched structure
// with predicated loads (neutral substitutes for invalid pairs) instead of
// the serial per-pair branch+log path.

#define NTHREADS 256
#define PPT 8                                   // float4-pairs per thread
#define CHUNK_PAIRS (NTHREADS * PPT)            // 2048 pairs / block
#define FP_SCALE 1048576.0f                     // 2^20

__device__ unsigned long long g_loss;           // fixed-point loss sum
__device__ int                g_len;            // doc_len sum
__device__ unsigned int       g_counter;        // zero-init; reset by last block

__global__ __launch_bounds__(NTHREADS)
void ce_fused_kernel(const float* __restrict__ y_true,
                     const float* __restrict__ y_pred,
                     const int*   __restrict__ doc_len,
                     float* __restrict__ out,
                     int B, int L, int chunksPerRow, int nBlocks)
{
    const int tid   = threadIdx.x;
    const int b     = blockIdx.x / chunksPerRow;
    const int chunk = blockIdx.x - b * chunksPerRow;
    const int d     = __ldg(&doc_len[b]);

    const int pairBase = chunk * CHUNK_PAIRS;
    const int lStart   = pairBase * 2;

    float acc = 0.0f;

    if (lStart < d) {
        const float4* t4 = reinterpret_cast<const float4*>(y_true) + (size_t)b * (L >> 1);
        const float4* p4 = reinterpret_cast<const float4*>(y_pred) + (size_t)b * (L >> 1);

        if (lStart + CHUNK_PAIRS * 2 <= d) {
            // ---- fully valid: batched loads, 8-way product, 1 log / 4 pairs ----
            float4 t[PPT], p[PPT];
            #pragma unroll
            for (int i = 0; i < PPT; i++)
                t[i] = __ldg(&t4[pairBase + i * NTHREADS + tid]);
            #pragma unroll
            for (int i = 0; i < PPT; i++)
                p[i] = __ldg(&p4[pairBase + i * NTHREADS + tid]);

            #pragma unroll
            for (int j = 0; j < PPT / 4; j++) {
                float m = 1.0f;
                #pragma unroll
                for (int i = 4 * j; i < 4 * j + 4; i++) {
                    float s0 = t[i].x * p[i].x + t[i].y * p[i].y;  // exact one-hot select
                    float s1 = t[i].z * p[i].z + t[i].w * p[i].w;
                    m *= s0 * s1;                // 8 factors >= 1e-4 -> m >= 1e-32
                }
                acc -= __logf(m);
            }
        } else {
            // ---- boundary chunk: SAME batched structure, predicated loads ----
            float4 t[PPT], p[PPT];
            #pragma unroll
            for (int i = 0; i < PPT; i++) {
                int pr = pairBase + i * NTHREADS + tid;
                if (2 * pr < d) {
                    t[i] = __ldg(&t4[pr]);
                    p[i] = __ldg(&p4[pr]);
                } else {                         // neutral: s0 = s1 = 1
                    t[i] = make_float4(1.0f, 0.0f, 1.0f, 0.0f);
                    p[i] = make_float4(1.0f, 1.0f, 1.0f, 1.0f);
                }
            }
            #pragma unroll
            for (int j = 0; j < PPT / 4; j++) {
                float m = 1.0f;
                #pragma unroll
                for (int i = 4 * j; i < 4 * j + 4; i++) {
                    int pr = pairBase + i * NTHREADS + tid;
                    float s0 = t[i].x * p[i].x + t[i].y * p[i].y;
                    float s1 = t[i].z * p[i].z + t[i].w * p[i].w;
                    s1 = (2 * pr + 1 < d) ? s1 : 1.0f;   // mask odd-tail position
                    m *= s0 * s1;
                }
                acc -= __logf(m);
            }
        }
    }

    // ---- block reduction ----
    __shared__ float red[NTHREADS / 32];
    #pragma unroll
    for (int o = 16; o > 0; o >>= 1)
        acc += __shfl_down_sync(0xFFFFFFFFu, acc, o);
    if ((tid & 31) == 0) red[tid >> 5] = acc;
    __syncthreads();

    // ---- atomic accumulation (exact integer adds -> deterministic) ----
    __shared__ bool amLast;
    if (tid == 0) {
        float v = 0.0f;
        #pragma unroll
        for (int i = 0; i < NTHREADS / 32; i++) v += red[i];
        unsigned long long q = (unsigned long long)__float2ll_rn(v * FP_SCALE);
        atomicAdd(&g_loss, q);
        if (chunk == 0) atomicAdd(&g_len, d);
        __threadfence();
        unsigned int prev = atomicAdd(&g_counter, 1u);
        amLast = (prev == (unsigned int)(nBlocks - 1));
    }
    __syncthreads();

    // ---- last block: finish from two scalars, reset for graph replay ----
    if (amLast && tid == 0) {
        unsigned long long ls = g_loss;
        int                ln = g_len;
        out[0] = (float)((double)ls / (double)FP_SCALE / (double)ln);
        g_loss    = 0ull;
        g_len     = 0;
        g_counter = 0;
    }
}

extern "C" void kernel_launch(void* const* d_in, const int* in_sizes, int n_in,
                              void* d_out, int out_size)
{
    const float* y_true  = (const float*)d_in[0];
    const float* y_pred  = (const float*)d_in[1];
    const int*   doc_len = (const int*)d_in[2];
    float*       out     = (float*)d_out;

    int B = in_sizes[2];
    int L = in_sizes[0] / (2 * B);

    int pairsPerRow  = L >> 1;
    int chunksPerRow = (pairsPerRow + CHUNK_PAIRS - 1) / CHUNK_PAIRS;
    int nBlocks      = B * chunksPerRow;

    ce_fused_kernel<<<nBlocks, NTHREADS>>>(y_true, y_pred, doc_len, out,
                                           B, L, chunksPerRow, nBlocks);
}